// round 7
// baseline (speedup 1.0000x reference)
#include <cuda_runtime.h>
#include <stdint.h>

#define NB   256
#define NK   64
#define NL   32
#define NM   (NK * NL)            // 2048 rows per (side, batch) block
#define NTOT (2 * NB * NM)        // 1,048,576 output rows
#define SENT 32
#define TBL  4096
#define TMASK 4095u
#define EMPTYV 0xFFFFFFFFu
#define NODE_MASK 0x1FFFFu        // node ids < 100000 < 2^17

#define CTAS 592                  // 4 * 148 SMs: exactly one co-resident wave
#define RPC  1772                 // ceil(NTOT / CTAS); slice spans <= 2 blocks

// resolved codes per row: own | cross<<6 | valid<<15.  2 MB -> L2-resident.
__device__ uint16_t g_code[NTOT];
// monotonic per-CTA epoch counters (never reset; +1 per slot per run) — replay-safe
__device__ unsigned g_ready[CTAS];

__device__ __forceinline__ int ht_lookup(const uint32_t* __restrict__ tab, uint32_t node) {
    uint32_t h = (node * 2654435761u) & TMASK;
    #pragma unroll 1
    for (;;) {
        uint32_t cur = tab[h];
        if (cur == EMPTYV) return SENT;
        if ((cur & NODE_MASK) == node) return (int)(cur >> 17);
        h = (h + 1) & TMASK;
    }
}

__global__ __launch_bounds__(512, 4) void wpe_kernel(
    const int* __restrict__ src_walks, const int* __restrict__ tgt_walks,
    const int* __restrict__ src_lens,  const int* __restrict__ tgt_lens,
    const float* __restrict__ own_emb, const float* __restrict__ cross_emb,
    float* __restrict__ out)
{
    __shared__ uint32_t s_tab[2][TBL];    // 32 KB (builders only)

    const int bid = blockIdx.x;
    const int tid = threadIdx.x;
    const int warp = tid >> 5, lane = tid & 31;
    const int half = lane >> 4, col = lane & 15;

    // ── phase 0: CTAs 0..255 build batch `bid`'s two tables + all 4096 codes ──
    if (bid < NB) {
        const int b = bid;
        for (int i = tid; i < 2 * TBL; i += 512)
            (&s_tab[0][0])[i] = EMPTYV;
        __syncthreads();

        #pragma unroll
        for (int t = 0; t < 2; t++) {
            const int* w  = (t == 0 ? src_walks : tgt_walks) + b * NM;
            const int* ln = (t == 0 ? src_lens  : tgt_lens)  + b * NK;
            uint32_t* tab = s_tab[t];
            #pragma unroll
            for (int r = 0; r < NM / 512; r++) {
                int m = tid + r * 512;
                int node = w[m];
                int l = m & (NL - 1);
                if (node != 0 && l < ln[m >> 5]) {
                    uint32_t packed = ((uint32_t)l << 17) | (uint32_t)node;
                    uint32_t h = ((uint32_t)node * 2654435761u) & TMASK;
                    #pragma unroll 1
                    for (;;) {
                        uint32_t cur = tab[h];
                        if (cur == EMPTYV) {
                            cur = atomicCAS(&tab[h], EMPTYV, packed);
                            if (cur == EMPTYV) break;
                        }
                        if ((cur & NODE_MASK) == (uint32_t)node) {
                            atomicMin(&tab[h], packed);   // same key: packed-min == pos-min
                            break;
                        }
                        h = (h + 1) & TMASK;
                    }
                }
            }
        }
        __syncthreads();

        // resolve codes for both sides of this batch; write to L2
        #pragma unroll
        for (int s = 0; s < 2; s++) {
            const int* w  = (s == 0 ? src_walks : tgt_walks) + b * NM;
            const int* ln = (s == 0 ? src_lens  : tgt_lens)  + b * NK;
            const uint32_t* mytab = s_tab[s];
            const uint32_t* xtab  = s_tab[s ^ 1];
            uint16_t* gc = g_code + ((size_t)s * NB + b) * NM;
            #pragma unroll
            for (int r = 0; r < NM / 512; r++) {
                int m = tid + r * 512;
                int node = w[m];
                int l = m & (NL - 1);
                uint16_t p = 0;
                if (node != 0 && l < ln[m >> 5]) {
                    int own   = ht_lookup(mytab, (uint32_t)node);
                    int cross = ht_lookup(xtab,  (uint32_t)node);
                    p = (uint16_t)(own | (cross << 6) | 0x8000);
                }
                gc[m] = p;
            }
        }
        __syncthreads();
    }

    // ── epoch publish + targeted wait (thread 0 only) ──
    long r0 = (long)bid * RPC;
    long r1 = r0 + RPC; if (r1 > NTOT) r1 = NTOT;
    const int cnt = (int)(r1 - r0);

    if (tid == 0) {
        __threadfence();                                   // publish g_code writes
        unsigned E = atomicAdd(&g_ready[bid], 1u) + 1u;    // consistent run epoch
        const int b0 = (int)((r0 >> 11) & (NB - 1));
        const int b1 = (int)(((r1 - 1) >> 11) & (NB - 1));
        while (*(volatile unsigned*)&g_ready[b0] < E) __nanosleep(32);
        if (b1 != b0)
            while (*(volatile unsigned*)&g_ready[b1] < E) __nanosleep(32);
        __threadfence();                                   // acquire
    }
    __syncthreads();

    // ── emit: one warp per row; codes read warp-uniform from L2/L1 ──
    const float4* oe = (const float4*)own_emb;     // 33 rows x 16 float4
    const float4* ce = (const float4*)cross_emb;
    float4* out4 = (float4*)out;

    int i = warp;
    for (; i + 64 <= cnt; i += 64) {               // 4-deep batches for store MLP
        uint32_t p[4]; float4 v[4];
        #pragma unroll
        for (int j = 0; j < 4; j++) p[j] = __ldg(&g_code[r0 + i + j * 16]);
        #pragma unroll
        for (int j = 0; j < 4; j++) {
            v[j] = make_float4(0.f, 0.f, 0.f, 0.f);
            if (p[j] & 0x8000u) {
                int own   = p[j] & 63;
                int cross = (p[j] >> 6) & 63;
                v[j] = half ? __ldg(&ce[cross * 16 + col])
                            : __ldg(&oe[own   * 16 + col]);
            }
        }
        #pragma unroll
        for (int j = 0; j < 4; j++)
            __stcs(&out4[(size_t)(r0 + i + j * 16) * 32 + lane], v[j]);
    }
    for (; i < cnt; i += 16) {                     // remainder
        uint32_t p = __ldg(&g_code[r0 + i]);
        float4 v = make_float4(0.f, 0.f, 0.f, 0.f);
        if (p & 0x8000u) {
            int own   = p & 63;
            int cross = (p >> 6) & 63;
            v = half ? __ldg(&ce[cross * 16 + col])
                     : __ldg(&oe[own   * 16 + col]);
        }
        __stcs(&out4[(size_t)(r0 + i) * 32 + lane], v);
    }
}

extern "C" void kernel_launch(void* const* d_in, const int* in_sizes, int n_in,
                              void* d_out, int out_size) {
    (void)in_sizes; (void)n_in; (void)out_size;
    wpe_kernel<<<CTAS, 512>>>(
        (const int*)d_in[0], (const int*)d_in[1],
        (const int*)d_in[2], (const int*)d_in[3],
        (const float*)d_in[4], (const float*)d_in[5],
        (float*)d_out);
}

// round 8
// speedup vs baseline: 1.0353x; 1.0353x over previous
#include <cuda_runtime.h>
#include <stdint.h>

#define NB   256
#define NK   64
#define NL   32
#define NM   (NK * NL)            // 2048 rows per (side, batch) block
#define NTOT (2 * NB * NM)        // 1,048,576 output rows
#define SENT 32
#define TBL  4096
#define TMASK 4095u
#define EMPTYV 0xFFFFFFFFu
#define NODE_MASK 0x1FFFFu        // node ids < 100000 < 2^17

#define CTAS 592                  // 4 * 148 SMs: one co-resident wave
#define RPC  1772                 // ceil(NTOT / CTAS); slice spans <= 2 batches
#define NTABS 512                 // one builder CTA per (side, batch) table

// first-seen tables (8 MB, L2-resident)
__device__ uint32_t g_tab[NTABS * TBL];
// monotonic per-CTA epoch slots: exactly +1 per slot per run -> replay-safe
__device__ unsigned g_ready[CTAS];

__device__ __forceinline__ int ht_lookup_g(const uint32_t* __restrict__ tab, uint32_t node) {
    uint32_t h = (node * 2654435761u) & TMASK;
    #pragma unroll 1
    for (;;) {
        uint32_t cur = __ldg(&tab[h]);
        if (cur == EMPTYV) return SENT;
        if ((cur & NODE_MASK) == node) return (int)(cur >> 17);
        h = (h + 1) & TMASK;
    }
}

__global__ __launch_bounds__(512, 4) void wpe_kernel(
    const int* __restrict__ src_walks, const int* __restrict__ tgt_walks,
    const int* __restrict__ src_lens,  const int* __restrict__ tgt_lens,
    const float* __restrict__ own_emb, const float* __restrict__ cross_emb,
    float* __restrict__ out)
{
    __shared__ uint32_t tab[TBL];         // 16 KB (builders only)
    __shared__ uint16_t s_code[RPC + 4];  // 3.5 KB resolved codes

    const int bid = blockIdx.x;
    const int tid = threadIdx.x;
    const int warp = tid >> 5, lane = tid & 31;
    const int half = lane >> 4, col = lane & 15;

    // ── stage 1: CTAs 0..511 each build ONE (side,batch) table, dump to L2 ──
    if (bid < NTABS) {
        const int s = bid >> 8, b = bid & (NB - 1);
        const int* w  = (s == 0 ? src_walks : tgt_walks) + b * NM;
        const int* ln = (s == 0 ? src_lens  : tgt_lens)  + b * NK;

        for (int i = tid; i < TBL; i += 512) tab[i] = EMPTYV;
        __syncthreads();

        #pragma unroll
        for (int r = 0; r < NM / 512; r++) {
            int m = tid + r * 512;
            int node = w[m];
            int l = m & (NL - 1);
            if (node != 0 && l < ln[m >> 5]) {
                uint32_t packed = ((uint32_t)l << 17) | (uint32_t)node;
                uint32_t h = ((uint32_t)node * 2654435761u) & TMASK;
                #pragma unroll 1
                for (;;) {
                    uint32_t cur = tab[h];
                    if (cur == EMPTYV) {
                        cur = atomicCAS(&tab[h], EMPTYV, packed);
                        if (cur == EMPTYV) break;
                    }
                    if ((cur & NODE_MASK) == (uint32_t)node) {
                        atomicMin(&tab[h], packed);   // same key: packed-min == pos-min
                        break;
                    }
                    h = (h + 1) & TMASK;
                }
            }
        }
        __syncthreads();

        uint4* dst = (uint4*)(g_tab + (size_t)bid * TBL);
        const uint4* srcv = (const uint4*)tab;
        #pragma unroll
        for (int i = tid; i < TBL / 4; i += 512) dst[i] = srcv[i];
    }
    __syncthreads();

    // ── epoch publish + targeted wait on the <=2 batches this slice touches ──
    long r0 = (long)bid * RPC;
    long r1 = r0 + RPC; if (r1 > NTOT) r1 = NTOT;
    const int cnt = (int)(r1 - r0);

    if (tid == 0) {
        __threadfence();                                   // publish g_tab dump
        unsigned E = atomicAdd(&g_ready[bid], 1u) + 1u;    // this run's epoch
        const int b0 = (int)((r0 >> 11) & (NB - 1));
        const int b1 = (int)(((r1 - 1) >> 11) & (NB - 1));
        while (*(volatile unsigned*)&g_ready[b0]      < E) __nanosleep(32);
        while (*(volatile unsigned*)&g_ready[256+b0]  < E) __nanosleep(32);
        if (b1 != b0) {
            while (*(volatile unsigned*)&g_ready[b1]     < E) __nanosleep(32);
            while (*(volatile unsigned*)&g_ready[256+b1] < E) __nanosleep(32);
        }
        __threadfence();                                   // acquire
    }
    __syncthreads();

    // ── stage 2a: resolve this slice's codes from L2 tables (cheap: R5 data) ──
    for (int i = tid; i < cnt; i += 512) {
        long r = r0 + i;
        const int s = (int)(r >> 19);
        const int b = (int)((r >> 11) & (NB - 1));
        const int m = (int)(r & (NM - 1));
        const int* w  = (s == 0 ? src_walks : tgt_walks) + b * NM;
        const int* ln = (s == 0 ? src_lens  : tgt_lens)  + b * NK;
        int node = w[m];
        int l = m & (NL - 1);
        uint16_t p = 0;
        if (node != 0 && l < ln[m >> 5]) {
            const uint32_t* mytab = g_tab + ((size_t)(s       * NB + b)) * TBL;
            const uint32_t* xtab  = g_tab + ((size_t)((s ^ 1) * NB + b)) * TBL;
            int own   = ht_lookup_g(mytab, (uint32_t)node);
            int cross = ht_lookup_g(xtab,  (uint32_t)node);
            p = (uint16_t)(own | (cross << 6) | 0x8000);
        }
        s_code[i] = p;
    }
    __syncthreads();

    // ── stage 2b: streaming emit — one warp per row, 32 lanes x float4 ──
    const float4* oe = (const float4*)own_emb;     // 33 rows x 16 float4
    const float4* ce = (const float4*)cross_emb;
    float4* out4 = (float4*)out;

    int i = warp;
    for (; i + 64 <= cnt; i += 64) {               // 4-deep batches for store MLP
        uint32_t p[4]; float4 v[4];
        #pragma unroll
        for (int j = 0; j < 4; j++) p[j] = s_code[i + j * 16];
        #pragma unroll
        for (int j = 0; j < 4; j++) {
            v[j] = make_float4(0.f, 0.f, 0.f, 0.f);
            if (p[j] & 0x8000u) {
                int own   = p[j] & 63;
                int cross = (p[j] >> 6) & 63;
                v[j] = half ? __ldg(&ce[cross * 16 + col])
                            : __ldg(&oe[own   * 16 + col]);
            }
        }
        #pragma unroll
        for (int j = 0; j < 4; j++)
            __stcs(&out4[(size_t)(r0 + i + j * 16) * 32 + lane], v[j]);
    }
    for (; i < cnt; i += 16) {                     // remainder
        uint32_t p = s_code[i];
        float4 v = make_float4(0.f, 0.f, 0.f, 0.f);
        if (p & 0x8000u) {
            int own   = p & 63;
            int cross = (p >> 6) & 63;
            v = half ? __ldg(&ce[cross * 16 + col])
                     : __ldg(&oe[own   * 16 + col]);
        }
        __stcs(&out4[(size_t)(r0 + i) * 32 + lane], v);
    }
}

extern "C" void kernel_launch(void* const* d_in, const int* in_sizes, int n_in,
                              void* d_out, int out_size) {
    (void)in_sizes; (void)n_in; (void)out_size;
    wpe_kernel<<<CTAS, 512>>>(
        (const int*)d_in[0], (const int*)d_in[1],
        (const int*)d_in[2], (const int*)d_in[3],
        (const float*)d_in[4], (const float*)d_in[5],
        (float*)d_out);
}